// round 3
// baseline (speedup 1.0000x reference)
#include <cuda_runtime.h>
#include <cuda_bf16.h>
#include <math.h>

#define T_STEPS 100000
#define S_DIM   200
#define N_DIM   215

// ---- device scratch (static; no runtime allocation) ----
__device__ float g_pre_f[T_STEPS * S_DIM];
__device__ float g_pre_i[T_STEPS * S_DIM];
__device__ float g_cand [T_STEPS * S_DIM];
__device__ float g_sfinal[S_DIM];
__device__ float g_xchg[2][2][S_DIM];     // [writer rank][parity][col]
__device__ unsigned g_flag[2][2];         // [writer rank][parity] = step+1

// ---- helpers ----
__device__ __forceinline__ unsigned long long pack2(float x, float y) {
    unsigned long long r;
    asm("mov.b64 %0, {%1, %2};" : "=l"(r) : "f"(x), "f"(y));
    return r;
}
__device__ __forceinline__ float2 unpack2(unsigned long long v) {
    float2 f;
    asm("mov.b64 {%0, %1}, %2;" : "=f"(f.x), "=f"(f.y) : "l"(v));
    return f;
}
#define FMA2(acc, a, b) \
    asm("fma.rn.f32x2 %0, %1, %2, %0;" : "+l"(acc) : "l"(a), "l"(b))

__device__ __forceinline__ void st_release_u32(unsigned* p, unsigned v) {
    asm volatile("st.release.gpu.global.u32 [%0], %1;" :: "l"(p), "r"(v) : "memory");
}
__device__ __forceinline__ unsigned ld_acquire_u32(const unsigned* p) {
    unsigned v;
    asm volatile("ld.acquire.gpu.global.u32 %0, [%1];" : "=r"(v) : "l"(p) : "memory");
    return v;
}

// ============================================================
// Phase 1: the three track GEMMs. grid (3125,3), block 256.
// ============================================================
#define TILE_T 32
#define KCHUNK 43   // 5*43 = 215

__global__ __launch_bounds__(256) void pre_kernel(
    const float* __restrict__ track,
    const float* __restrict__ Wf, const float* __restrict__ bf,
    const float* __restrict__ Wi, const float* __restrict__ bi,
    const float* __restrict__ Wc, const float* __restrict__ bc)
{
    __shared__ float sW[KCHUNK * S_DIM];
    __shared__ float sT[TILE_T * KCHUNK];
    const int mat = blockIdx.y;
    const int t0  = blockIdx.x * TILE_T;
    const int tid = threadIdx.x;
    const float* W   = (mat == 0) ? Wf : (mat == 1) ? Wi : Wc;
    const float* bia = (mat == 0) ? bf : (mat == 1) ? bi : bc;
    float* out       = (mat == 0) ? g_pre_f : (mat == 1) ? g_pre_i : g_cand;

    float acc[TILE_T];
    #pragma unroll
    for (int i = 0; i < TILE_T; i++) acc[i] = 0.0f;

    for (int c = 0; c < 5; c++) {
        const int k0 = c * KCHUNK;
        for (int idx = tid; idx < KCHUNK * S_DIM; idx += 256) {
            int r = idx / S_DIM, col = idx - r * S_DIM;
            sW[idx] = W[(k0 + r) * S_DIM + col];
        }
        for (int idx = tid; idx < TILE_T * KCHUNK; idx += 256) {
            int tt = idx / KCHUNK, kk = idx - tt * KCHUNK;
            sT[idx] = track[(t0 + tt) * N_DIM + k0 + kk];
        }
        __syncthreads();
        if (tid < S_DIM) {
            for (int kk = 0; kk < KCHUNK; kk++) {
                float wv = sW[kk * S_DIM + tid];
                #pragma unroll
                for (int tt = 0; tt < TILE_T; tt++)
                    acc[tt] = fmaf(sT[tt * KCHUNK + kk], wv, acc[tt]);
            }
        }
        __syncthreads();
    }
    if (tid < S_DIM) {
        float bv = bia[tid];
        #pragma unroll 4
        for (int tt = 0; tt < TILE_T; tt++) {
            float v = acc[tt] + bv;
            if (mat == 2) v = tanhf(v);
            out[(t0 + tt) * S_DIM + tid] = v;
        }
    }
}

// ============================================================
// Reset handshake flags (fresh per graph replay).
// ============================================================
__global__ void reset_kernel() {
    if (threadIdx.x < 4) ((unsigned*)g_flag)[threadIdx.x] = 0;
}

// ============================================================
// Phase 2: sequential scan. grid(2), block 416.
// rank0: u = s * sigmoid(pre_f + s@Wf_s)
// rank1: v = sigmoid(pre_i + s@Wi_s) * cand
// s_new = u + v, exchanged via L2 + release/acquire flags.
// ============================================================
__global__ void __launch_bounds__(416, 1) scan_kernel(
    const float* __restrict__ Wf, const float* __restrict__ Wi,
    const float* __restrict__ state0)
{
    __shared__ __align__(16) float s_state[S_DIM];
    __shared__ float s_part[S_DIM];
    const int tid  = threadIdx.x;
    const int rank = blockIdx.x;
    const int peer = rank ^ 1;

    const bool act  = (tid < 400);
    const int  j    = act ? (tid >> 1) : 0;
    const int  h    = tid & 1;
    const bool own  = act && (h == 0);

    // load this CTA's recurrent matrix into registers (50 f32x2 pairs/thread)
    const float* W = (rank == 0) ? Wf : Wi;
    const int kbase = N_DIM + h * 100;
    unsigned long long w[50];
    #pragma unroll
    for (int i = 0; i < 50; i++) {
        float a = act ? W[(kbase + 2 * i    ) * S_DIM + j] : 0.0f;
        float b = act ? W[(kbase + 2 * i + 1) * S_DIM + j] : 0.0f;
        w[i] = pack2(a, b);
    }

    if (tid < S_DIM) s_state[tid] = state0[tid];
    __syncthreads();

    const float* pre = (rank == 0) ? g_pre_f : g_pre_i;
    float p_cur = 0.0f, c_cur = 0.0f;
    if (own) {
        p_cur = __ldcg(pre + j);
        if (rank == 1) c_cur = __ldcg(g_cand + j);
    }

    for (int t = 0; t < T_STEPS; t++) {
        // prefetch next step's streams
        float p_next = 0.0f, c_next = 0.0f;
        if (own) {
            int tn = (t + 1 < T_STEPS) ? (t + 1) : (T_STEPS - 1);
            p_next = __ldcg(pre + tn * S_DIM + j);
            if (rank == 1) c_next = __ldcg(g_cand + tn * S_DIM + j);
        }

        // matvec: 100 MACs/thread as 50 packed f32x2 FMAs
        unsigned long long a0 = 0ull, a1 = 0ull;
        const ulonglong2* s4 = (const ulonglong2*)s_state + h * 25;
        #pragma unroll
        for (int i = 0; i < 25; i++) {
            ulonglong2 sv = s4[i];
            FMA2(a0, w[2 * i    ], sv.x);
            FMA2(a1, w[2 * i + 1], sv.y);
        }
        float2 f0 = unpack2(a0), f1 = unpack2(a1);
        float zp = (f0.x + f0.y) + (f1.x + f1.y);
        float z  = zp + __shfl_xor_sync(0xFFFFFFFFu, zp, 1);

        const int par = t & 1;
        if (own) {
            z += p_cur;
            float g = 1.0f / (1.0f + __expf(-z));
            float contrib = (rank == 0) ? (s_state[j] * g) : (g * c_cur);
            g_xchg[rank][par][j] = contrib;   // write-through to L2
            s_part[j] = contrib;
        }
        __syncthreads();
        if (tid == 0) {
            __threadfence();
            st_release_u32(&g_flag[rank][par], (unsigned)(t + 1));
            while (ld_acquire_u32(&g_flag[peer][par]) < (unsigned)(t + 1)) { }
        }
        __syncthreads();
        if (tid < S_DIM)
            s_state[tid] = s_part[tid] + __ldcg(&g_xchg[peer][par][tid]);
        __syncthreads();

        p_cur = p_next; c_cur = c_next;
    }

    if (rank == 0 && tid < S_DIM) g_sfinal[tid] = s_state[tid];
}

// ============================================================
// Phase 3: output head. 1 block, 256 threads.
// ============================================================
__global__ __launch_bounds__(256) void head_kernel(
    const float* __restrict__ W1, const float* __restrict__ b1,
    const float* __restrict__ W2, const float* __restrict__ b2,
    float* __restrict__ out)
{
    __shared__ float s_s[S_DIM], s_h[S_DIM], s_red[256];
    const int tid = threadIdx.x;
    if (tid < S_DIM) s_s[tid] = g_sfinal[tid];
    __syncthreads();

    if (tid < S_DIM) {
        float a = b1[tid];
        for (int k = 0; k < S_DIM; k++) a = fmaf(s_s[k], W1[k * S_DIM + tid], a);
        s_h[tid] = fmaxf(a, 0.0f);
    }
    __syncthreads();
    float h2 = 0.0f;
    if (tid < S_DIM) {
        float a = b2[tid];
        for (int k = 0; k < S_DIM; k++) a = fmaf(s_h[k], W2[k * S_DIM + tid], a);
        h2 = fmaxf(a, 0.0f);
    }
    // max reduction
    s_red[tid] = (tid < S_DIM) ? h2 : -1e30f;
    __syncthreads();
    for (int s = 128; s > 0; s >>= 1) {
        if (tid < s) s_red[tid] = fmaxf(s_red[tid], s_red[tid + s]);
        __syncthreads();
    }
    float m = s_red[0];
    __syncthreads();
    // sum(exp) reduction
    s_red[tid] = (tid < S_DIM) ? expf(h2 - m) : 0.0f;
    __syncthreads();
    for (int s = 128; s > 0; s >>= 1) {
        if (tid < s) s_red[tid] += s_red[tid + s];
        __syncthreads();
    }
    float lse = logf(s_red[0]);
    if (tid < S_DIM) out[tid] = h2 - m - lse;
}

// ============================================================
extern "C" void kernel_launch(void* const* d_in, const int* in_sizes, int n_in,
                              void* d_out, int out_size) {
    const float* track  = (const float*)d_in[0];
    const float* state0 = (const float*)d_in[1];
    const float* Wf     = (const float*)d_in[2];
    const float* bf     = (const float*)d_in[3];
    const float* Wi     = (const float*)d_in[4];
    const float* bi     = (const float*)d_in[5];
    const float* Wc     = (const float*)d_in[6];
    const float* bc     = (const float*)d_in[7];
    const float* W1     = (const float*)d_in[8];
    const float* b1     = (const float*)d_in[9];
    const float* W2     = (const float*)d_in[10];
    const float* b2     = (const float*)d_in[11];
    float* out = (float*)d_out;

    dim3 g(T_STEPS / TILE_T, 3);
    pre_kernel<<<g, 256>>>(track, Wf, bf, Wi, bi, Wc, bc);
    reset_kernel<<<1, 32>>>();
    scan_kernel<<<2, 416>>>(Wf, Wi, state0);
    head_kernel<<<1, 256>>>(W1, b1, W2, b2, out);
}

// round 6
// speedup vs baseline: 1.2639x; 1.2639x over previous
#include <cuda_runtime.h>
#include <cuda_bf16.h>
#include <math.h>

#define T_STEPS 100000
#define S_DIM   200
#define N_DIM   215

// ---- device scratch (static; no runtime allocation) ----
__device__ float g_pre_f[T_STEPS * S_DIM];
__device__ float g_pre_i[T_STEPS * S_DIM];
__device__ float g_cand [T_STEPS * S_DIM];
__device__ float g_sfinal[S_DIM];
// tagged exchange packets: hi32 = step tag (t+1), lo32 = float payload
__device__ __align__(8) unsigned long long g_xchg[2][S_DIM];

// ---- helpers ----
__device__ __forceinline__ unsigned long long pack2(float x, float y) {
    unsigned long long r;
    asm("mov.b64 %0, {%1, %2};" : "=l"(r) : "f"(x), "f"(y));
    return r;
}
__device__ __forceinline__ float2 unpack2(unsigned long long v) {
    float2 f;
    asm("mov.b64 {%0, %1}, %2;" : "=f"(f.x), "=f"(f.y) : "l"(v));
    return f;
}
#define FMA2(acc, a, b) \
    asm("fma.rn.f32x2 %0, %1, %2, %0;" : "+l"(acc) : "l"(a), "l"(b))

__device__ __forceinline__ void st_relaxed_b64(unsigned long long* p,
                                               unsigned long long v) {
    asm volatile("st.relaxed.gpu.global.b64 [%0], %1;"
                 :: "l"(p), "l"(v) : "memory");
}
__device__ __forceinline__ unsigned long long ld_relaxed_b64(
    const unsigned long long* p) {
    unsigned long long v;
    asm volatile("ld.relaxed.gpu.global.b64 %0, [%1];"
                 : "=l"(v) : "l"(p) : "memory");
    return v;
}
__device__ __forceinline__ unsigned long long tag_pack(unsigned tag, float val) {
    unsigned long long r;
    asm("mov.b64 %0, {%1, %2};" : "=l"(r) : "f"(val), "r"(tag));
    return r;  // lo = val, hi = tag
}

// ============================================================
// Phase 1: the three track GEMMs. grid (3125,3), block 256.
// ============================================================
#define TILE_T 32
#define KCHUNK 43   // 5*43 = 215

__global__ __launch_bounds__(256) void pre_kernel(
    const float* __restrict__ track,
    const float* __restrict__ Wf, const float* __restrict__ bf,
    const float* __restrict__ Wi, const float* __restrict__ bi,
    const float* __restrict__ Wc, const float* __restrict__ bc)
{
    __shared__ float sW[KCHUNK * S_DIM];
    __shared__ float sT[TILE_T * KCHUNK];
    const int mat = blockIdx.y;
    const int t0  = blockIdx.x * TILE_T;
    const int tid = threadIdx.x;
    const float* W   = (mat == 0) ? Wf : (mat == 1) ? Wi : Wc;
    const float* bia = (mat == 0) ? bf : (mat == 1) ? bi : bc;
    float* out       = (mat == 0) ? g_pre_f : (mat == 1) ? g_pre_i : g_cand;

    float acc[TILE_T];
    #pragma unroll
    for (int i = 0; i < TILE_T; i++) acc[i] = 0.0f;

    for (int c = 0; c < 5; c++) {
        const int k0 = c * KCHUNK;
        for (int idx = tid; idx < KCHUNK * S_DIM; idx += 256) {
            int r = idx / S_DIM, col = idx - r * S_DIM;
            sW[idx] = W[(k0 + r) * S_DIM + col];
        }
        for (int idx = tid; idx < TILE_T * KCHUNK; idx += 256) {
            int tt = idx / KCHUNK, kk = idx - tt * KCHUNK;
            sT[idx] = track[(t0 + tt) * N_DIM + k0 + kk];
        }
        __syncthreads();
        if (tid < S_DIM) {
            for (int kk = 0; kk < KCHUNK; kk++) {
                float wv = sW[kk * S_DIM + tid];
                #pragma unroll
                for (int tt = 0; tt < TILE_T; tt++)
                    acc[tt] = fmaf(sT[tt * KCHUNK + kk], wv, acc[tt]);
            }
        }
        __syncthreads();
    }
    if (tid < S_DIM) {
        float bv = bia[tid];
        #pragma unroll 4
        for (int tt = 0; tt < TILE_T; tt++) {
            float v = acc[tt] + bv;
            if (mat == 2) v = tanhf(v);
            out[(t0 + tt) * S_DIM + tid] = v;
        }
    }
}

// ============================================================
// Reset exchange tags (fresh per graph replay).
// ============================================================
__global__ void reset_kernel() {
    int i = threadIdx.x;
    if (i < 2 * S_DIM) ((unsigned long long*)g_xchg)[i] = 0ull;
}

// ============================================================
// Phase 2: sequential scan. grid(2), block 416. NO clusters.
// rank0: u = s * sigmoid(pre_f + s@Wf_s)
// rank1: v = sigmoid(pre_i + s@Wi_s) * cand
// s_new = u + v. Exchange: each owner thread stores one tagged
// b64 packet {tag=t+1, value} (single-copy-atomic) to L2; the
// peer owner polls its own column's packet. Data is its own
// readiness flag -> one L2 round trip, no fences, no serial tid0.
// ============================================================
__global__ void __launch_bounds__(416, 1) scan_kernel(
    const float* __restrict__ Wf, const float* __restrict__ Wi,
    const float* __restrict__ state0)
{
    __shared__ __align__(16) float s_state[S_DIM];
    const int tid  = threadIdx.x;
    const int rank = blockIdx.x;
    const int peer = rank ^ 1;

    const bool act = (tid < 400);
    const int  j   = act ? (tid >> 1) : 0;   // output column
    const int  h   = tid & 1;                // k-half
    const bool own = act && (h == 0);

    // ---- load this CTA's recurrent matrix into registers ----
    const float* W = (rank == 0) ? Wf : Wi;  // rows [215,415) = recurrent part
    const int kbase = N_DIM + h * 100;
    unsigned long long w[50];
    #pragma unroll
    for (int i = 0; i < 50; i++) {
        float a = act ? W[(kbase + 2 * i    ) * S_DIM + j] : 0.0f;
        float b = act ? W[(kbase + 2 * i + 1) * S_DIM + j] : 0.0f;
        w[i] = pack2(a, b);
    }

    if (tid < S_DIM) s_state[tid] = state0[tid];
    __syncthreads();

    const float* pre = (rank == 0) ? g_pre_f : g_pre_i;
    float p_cur = 0.0f, c_cur = 0.0f;
    if (own) {
        p_cur = __ldcg(pre + j);
        if (rank == 1) c_cur = __ldcg(g_cand + j);
    }

    unsigned long long* my_slot   = own ? &g_xchg[rank][j] : &g_xchg[rank][0];
    unsigned long long* peer_slot = own ? &g_xchg[peer][j] : &g_xchg[peer][0];

    for (int t = 0; t < T_STEPS; t++) {
        // prefetch next step's streams (hides DRAM latency)
        float p_next = 0.0f, c_next = 0.0f;
        if (own) {
            int tn = (t + 1 < T_STEPS) ? (t + 1) : (T_STEPS - 1);
            p_next = __ldcg(pre + tn * S_DIM + j);
            if (rank == 1) c_next = __ldcg(g_cand + tn * S_DIM + j);
        }

        // ---- matvec: 100 MACs/thread as 50 packed f32x2 FMAs ----
        unsigned long long a0 = 0ull, a1 = 0ull;
        const ulonglong2* s4 = (const ulonglong2*)s_state + h * 25;
        #pragma unroll
        for (int i = 0; i < 25; i++) {
            ulonglong2 sv = s4[i];
            FMA2(a0, w[2 * i    ], sv.x);
            FMA2(a1, w[2 * i + 1], sv.y);
        }
        float2 f0 = unpack2(a0), f1 = unpack2(a1);
        float zp = (f0.x + f0.y) + (f1.x + f1.y);
        float z  = zp + __shfl_xor_sync(0xFFFFFFFFu, zp, 1);

        const unsigned tag = (unsigned)(t + 1);
        if (own) {
            z += p_cur;
            float g = __fdividef(1.0f, 1.0f + __expf(-z));
            float contrib = (rank == 0) ? (s_state[j] * g) : (g * c_cur);

            // publish my contribution (tag + value travel together)
            st_relaxed_b64(my_slot, tag_pack(tag, contrib));

            // poll for the peer's contribution for this step
            unsigned long long pkt = ld_relaxed_b64(peer_slot);
            while ((unsigned)(pkt >> 32) != tag)
                pkt = ld_relaxed_b64(peer_slot);
            float pv = __uint_as_float((unsigned)pkt);

            s_state[j] = contrib + pv;
        }
        __syncthreads();

        p_cur = p_next; c_cur = c_next;
    }

    if (rank == 0 && tid < S_DIM) g_sfinal[tid] = s_state[tid];
}

// ============================================================
// Phase 3: output head. 1 block, 256 threads.
// ============================================================
__global__ __launch_bounds__(256) void head_kernel(
    const float* __restrict__ W1, const float* __restrict__ b1,
    const float* __restrict__ W2, const float* __restrict__ b2,
    float* __restrict__ out)
{
    __shared__ float s_s[S_DIM], s_h[S_DIM], s_red[256];
    const int tid = threadIdx.x;
    if (tid < S_DIM) s_s[tid] = g_sfinal[tid];
    __syncthreads();

    if (tid < S_DIM) {
        float a = b1[tid];
        for (int k = 0; k < S_DIM; k++) a = fmaf(s_s[k], W1[k * S_DIM + tid], a);
        s_h[tid] = fmaxf(a, 0.0f);
    }
    __syncthreads();
    float h2 = 0.0f;
    if (tid < S_DIM) {
        float a = b2[tid];
        for (int k = 0; k < S_DIM; k++) a = fmaf(s_h[k], W2[k * S_DIM + tid], a);
        h2 = fmaxf(a, 0.0f);
    }
    s_red[tid] = (tid < S_DIM) ? h2 : -1e30f;
    __syncthreads();
    for (int s = 128; s > 0; s >>= 1) {
        if (tid < s) s_red[tid] = fmaxf(s_red[tid], s_red[tid + s]);
        __syncthreads();
    }
    float m = s_red[0];
    __syncthreads();
    s_red[tid] = (tid < S_DIM) ? expf(h2 - m) : 0.0f;
    __syncthreads();
    for (int s = 128; s > 0; s >>= 1) {
        if (tid < s) s_red[tid] += s_red[tid + s];
        __syncthreads();
    }
    float lse = logf(s_red[0]);
    if (tid < S_DIM) out[tid] = h2 - m - lse;
}

// ============================================================
extern "C" void kernel_launch(void* const* d_in, const int* in_sizes, int n_in,
                              void* d_out, int out_size) {
    const float* track  = (const float*)d_in[0];
    const float* state0 = (const float*)d_in[1];
    const float* Wf     = (const float*)d_in[2];
    const float* bf     = (const float*)d_in[3];
    const float* Wi     = (const float*)d_in[4];
    const float* bi     = (const float*)d_in[5];
    const float* Wc     = (const float*)d_in[6];
    const float* bc     = (const float*)d_in[7];
    const float* W1     = (const float*)d_in[8];
    const float* b1     = (const float*)d_in[9];
    const float* W2     = (const float*)d_in[10];
    const float* b2     = (const float*)d_in[11];
    float* out = (float*)d_out;

    dim3 g(T_STEPS / TILE_T, 3);
    pre_kernel<<<g, 256>>>(track, Wf, bf, Wi, bi, Wc, bc);
    reset_kernel<<<1, 416>>>();
    scan_kernel<<<2, 416>>>(Wf, Wi, state0);
    head_kernel<<<1, 256>>>(W1, b1, W2, b2, out);
}

// round 7
// speedup vs baseline: 1.5611x; 1.2352x over previous
#include <cuda_runtime.h>
#include <cuda_bf16.h>
#include <math.h>

#define T_STEPS 100000
#define S_DIM   200
#define N_DIM   215

// ---- device scratch (static; no runtime allocation) ----
__device__ float g_pre_f[T_STEPS * S_DIM];
__device__ float g_pre_i[T_STEPS * S_DIM];
__device__ float g_cand [T_STEPS * S_DIM];
__device__ float g_sfinal[S_DIM];

// ---- helpers ----
__device__ __forceinline__ unsigned smem_u32(const void* p) {
    unsigned a;
    asm("{ .reg .u64 t; cvta.to.shared.u64 t, %1; cvt.u32.u64 %0, t; }"
        : "=r"(a) : "l"(p));
    return a;
}
__device__ __forceinline__ unsigned mapa_u32(unsigned a, unsigned rank) {
    unsigned d;
    asm("mapa.shared::cluster.u32 %0, %1, %2;" : "=r"(d) : "r"(a), "r"(rank));
    return d;
}
__device__ __forceinline__ void st_shared_cluster_f32(unsigned addr, float v) {
    asm volatile("st.shared::cluster.f32 [%0], %1;"
                 :: "r"(addr), "f"(v) : "memory");
}
__device__ __forceinline__ unsigned long long pack2(float x, float y) {
    unsigned long long r;
    asm("mov.b64 %0, {%1, %2};" : "=l"(r) : "f"(x), "f"(y));
    return r;
}
__device__ __forceinline__ float2 unpack2(unsigned long long v) {
    float2 f;
    asm("mov.b64 {%0, %1}, %2;" : "=f"(f.x), "=f"(f.y) : "l"(v));
    return f;
}
#define FMA2(acc, a, b) \
    asm("fma.rn.f32x2 %0, %1, %2, %0;" : "+l"(acc) : "l"(a), "l"(b))

#define CLUSTER_ARRIVE() \
    asm volatile("barrier.cluster.arrive.aligned;" ::: "memory")
#define CLUSTER_WAIT() \
    asm volatile("barrier.cluster.wait.aligned;" ::: "memory")

// ============================================================
// Phase 1: the three track GEMMs. grid (3125,3), block 256.
// ============================================================
#define TILE_T 32
#define KCHUNK 43   // 5*43 = 215

__global__ __launch_bounds__(256) void pre_kernel(
    const float* __restrict__ track,
    const float* __restrict__ Wf, const float* __restrict__ bf,
    const float* __restrict__ Wi, const float* __restrict__ bi,
    const float* __restrict__ Wc, const float* __restrict__ bc)
{
    __shared__ float sW[KCHUNK * S_DIM];
    __shared__ float sT[TILE_T * KCHUNK];
    const int mat = blockIdx.y;
    const int t0  = blockIdx.x * TILE_T;
    const int tid = threadIdx.x;
    const float* W   = (mat == 0) ? Wf : (mat == 1) ? Wi : Wc;
    const float* bia = (mat == 0) ? bf : (mat == 1) ? bi : bc;
    float* out       = (mat == 0) ? g_pre_f : (mat == 1) ? g_pre_i : g_cand;

    float acc[TILE_T];
    #pragma unroll
    for (int i = 0; i < TILE_T; i++) acc[i] = 0.0f;

    for (int c = 0; c < 5; c++) {
        const int k0 = c * KCHUNK;
        for (int idx = tid; idx < KCHUNK * S_DIM; idx += 256) {
            int r = idx / S_DIM, col = idx - r * S_DIM;
            sW[idx] = W[(k0 + r) * S_DIM + col];
        }
        for (int idx = tid; idx < TILE_T * KCHUNK; idx += 256) {
            int tt = idx / KCHUNK, kk = idx - tt * KCHUNK;
            sT[idx] = track[(t0 + tt) * N_DIM + k0 + kk];
        }
        __syncthreads();
        if (tid < S_DIM) {
            for (int kk = 0; kk < KCHUNK; kk++) {
                float wv = sW[kk * S_DIM + tid];
                #pragma unroll
                for (int tt = 0; tt < TILE_T; tt++)
                    acc[tt] = fmaf(sT[tt * KCHUNK + kk], wv, acc[tt]);
            }
        }
        __syncthreads();
    }
    if (tid < S_DIM) {
        float bv = bia[tid];
        #pragma unroll 4
        for (int tt = 0; tt < TILE_T; tt++) {
            float v = acc[tt] + bv;
            if (mat == 2) v = tanhf(v);
            out[(t0 + tt) * S_DIM + tid] = v;
        }
    }
}

// ============================================================
// Phase 2: sequential scan. 2-CTA cluster, 416 threads/CTA.
// rank0: u = s * sigmoid(pre_f + s@Wf_s)
// rank1: v = sigmoid(pre_i + s@Wi_s) * cand
// s_new = u + v. Exchange: plain remote st.shared::cluster into
// the peer's s_recv (double-buffered by step parity), ordered by
// one barrier.cluster (release/acquire) per step. No mbarriers,
// no polling, structurally deadlock-free.
// ============================================================
__global__ void __cluster_dims__(2, 1, 1) __launch_bounds__(416, 1)
scan_kernel(const float* __restrict__ Wf, const float* __restrict__ Wi,
            const float* __restrict__ state0)
{
    __shared__ __align__(16) float s_state[S_DIM];
    __shared__ __align__(16) float s_recv[2][S_DIM];

    const int tid = threadIdx.x;
    unsigned rank;
    asm("mov.u32 %0, %%cluster_ctarank;" : "=r"(rank));
    const unsigned peerR = rank ^ 1u;

    const bool act = (tid < 400);
    const int  j   = act ? (tid >> 1) : 0;   // output column
    const int  h   = tid & 1;                // k-half
    const bool own = act && (h == 0);

    // ---- load this CTA's recurrent matrix into registers ----
    const float* W = (rank == 0) ? Wf : Wi;  // rows [215,415) = recurrent part
    const int kbase = N_DIM + h * 100;
    unsigned long long w[50];
    #pragma unroll
    for (int i = 0; i < 50; i++) {
        float a = act ? W[(kbase + 2 * i    ) * S_DIM + j] : 0.0f;
        float b = act ? W[(kbase + 2 * i + 1) * S_DIM + j] : 0.0f;
        w[i] = pack2(a, b);
    }

    if (tid < S_DIM) s_state[tid] = state0[tid];
    __syncthreads();

    // peer addresses for this owner's column, both parity buffers
    const unsigned pd0 = mapa_u32(smem_u32(&s_recv[0][j]), peerR);
    const unsigned pd1 = mapa_u32(smem_u32(&s_recv[1][j]), peerR);

    const float* pre = (rank == 0) ? g_pre_f : g_pre_i;
    float p_cur = 0.0f, c_cur = 0.0f;
    if (own) {
        p_cur = __ldcg(pre + j);
        if (rank == 1) c_cur = __ldcg(g_cand + j);
    }

    for (int t = 0; t < T_STEPS; t++) {
        const int b = t & 1;

        // prefetch next step's streams (hides DRAM latency)
        float p_next = 0.0f, c_next = 0.0f;
        if (own) {
            int tn = (t + 1 < T_STEPS) ? (t + 1) : (T_STEPS - 1);
            p_next = __ldcg(pre + tn * S_DIM + j);
            if (rank == 1) c_next = __ldcg(g_cand + tn * S_DIM + j);
        }

        // ---- matvec: 100 MACs/thread as 50 packed f32x2 FMAs ----
        unsigned long long a0 = 0ull, a1 = 0ull;
        const ulonglong2* s4 = (const ulonglong2*)s_state + h * 25;
        #pragma unroll
        for (int i = 0; i < 25; i++) {
            ulonglong2 sv = s4[i];
            FMA2(a0, w[2 * i    ], sv.x);
            FMA2(a1, w[2 * i + 1], sv.y);
        }
        float2 f0 = unpack2(a0), f1 = unpack2(a1);
        float zp = (f0.x + f0.y) + (f1.x + f1.y);
        float z  = zp + __shfl_xor_sync(0xFFFFFFFFu, zp, 1);

        float contrib = 0.0f;
        if (own) {
            z += p_cur;
            float g = __fdividef(1.0f, 1.0f + __expf(-z));
            contrib = (rank == 0) ? (s_state[j] * g) : (g * c_cur);
            // push my contribution straight into the peer's smem
            st_shared_cluster_f32(b ? pd1 : pd0, contrib);
        }

        // one cluster barrier: orders remote stores (release/acquire)
        // and synchronizes both CTAs for this step
        CLUSTER_ARRIVE();
        CLUSTER_WAIT();

        if (own) s_state[j] = contrib + s_recv[b][j];
        __syncthreads();

        p_cur = p_next; c_cur = c_next;
    }

    if (rank == 0 && tid < S_DIM) g_sfinal[tid] = s_state[tid];
    CLUSTER_ARRIVE();
    CLUSTER_WAIT();
}

// ============================================================
// Phase 3: output head. 1 block, 256 threads.
// ============================================================
__global__ __launch_bounds__(256) void head_kernel(
    const float* __restrict__ W1, const float* __restrict__ b1,
    const float* __restrict__ W2, const float* __restrict__ b2,
    float* __restrict__ out)
{
    __shared__ float s_s[S_DIM], s_h[S_DIM], s_red[256];
    const int tid = threadIdx.x;
    if (tid < S_DIM) s_s[tid] = g_sfinal[tid];
    __syncthreads();

    if (tid < S_DIM) {
        float a = b1[tid];
        for (int k = 0; k < S_DIM; k++) a = fmaf(s_s[k], W1[k * S_DIM + tid], a);
        s_h[tid] = fmaxf(a, 0.0f);
    }
    __syncthreads();
    float h2 = 0.0f;
    if (tid < S_DIM) {
        float a = b2[tid];
        for (int k = 0; k < S_DIM; k++) a = fmaf(s_h[k], W2[k * S_DIM + tid], a);
        h2 = fmaxf(a, 0.0f);
    }
    s_red[tid] = (tid < S_DIM) ? h2 : -1e30f;
    __syncthreads();
    for (int s = 128; s > 0; s >>= 1) {
        if (tid < s) s_red[tid] = fmaxf(s_red[tid], s_red[tid + s]);
        __syncthreads();
    }
    float m = s_red[0];
    __syncthreads();
    s_red[tid] = (tid < S_DIM) ? expf(h2 - m) : 0.0f;
    __syncthreads();
    for (int s = 128; s > 0; s >>= 1) {
        if (tid < s) s_red[tid] += s_red[tid + s];
        __syncthreads();
    }
    float lse = logf(s_red[0]);
    if (tid < S_DIM) out[tid] = h2 - m - lse;
}

// ============================================================
extern "C" void kernel_launch(void* const* d_in, const int* in_sizes, int n_in,
                              void* d_out, int out_size) {
    const float* track  = (const float*)d_in[0];
    const float* state0 = (const float*)d_in[1];
    const float* Wf     = (const float*)d_in[2];
    const float* bf     = (const float*)d_in[3];
    const float* Wi     = (const float*)d_in[4];
    const float* bi     = (const float*)d_in[5];
    const float* Wc     = (const float*)d_in[6];
    const float* bc     = (const float*)d_in[7];
    const float* W1     = (const float*)d_in[8];
    const float* b1     = (const float*)d_in[9];
    const float* W2     = (const float*)d_in[10];
    const float* b2     = (const float*)d_in[11];
    float* out = (float*)d_out;

    dim3 g(T_STEPS / TILE_T, 3);
    pre_kernel<<<g, 256>>>(track, Wf, bf, Wi, bi, Wc, bc);
    scan_kernel<<<2, 416>>>(Wf, Wi, state0);
    head_kernel<<<1, 256>>>(W1, b1, W2, b2, out);
}